// round 9
// baseline (speedup 1.0000x reference)
#include <cuda_runtime.h>
#include <cstdint>
#include <math.h>

#define NMAX  100000
#define EMAX  3200000
#define FIN   128
#define C1    16
#define C2    8
#define NPB   64
#define SCAN_B 1024   // elements per scan block
#define NBMAX  ((NMAX + SCAN_B - 1) / SCAN_B)   // 98

// Scratch (device globals; allocation-free per harness rules)
__device__ __align__(16) int   g_cnt [NMAX];       // degree (no self loop)
__device__ __align__(16) int   g_off [NMAX];       // CSR exclusive offsets
__device__ __align__(16) int   g_cur [NMAX];       // build cursors
__device__ __align__(16) int   g_bsum[NBMAX];      // scan block sums
__device__ __align__(16) float g_dinv[NMAX];
__device__ __align__(16) int2  g_bin [EMAX];       // {src, bitcast(w)}
__device__ __align__(16) float g_u   [NMAX * C2];  // u = x @ M
__device__ __align__(16) float g_v   [NMAX * C2];  // v = A_hat u
__device__ __align__(16) float g_z   [NMAX];
__device__ __align__(16) float g_M   [FIN * C2];   // W1 @ W2
__device__ float g_alpha, g_beta;

__device__ __forceinline__ void cp_async16(unsigned int saddr, const void* gaddr) {
    asm volatile("cp.async.cg.shared.global [%0], [%1], 16;\n"
                 :: "r"(saddr), "l"(gaddr) : "memory");
}

// ---------------------------------------------------------------------------
// K0: zero degree counters + fold weights
__global__ void k_init(const float* __restrict__ W1, const float* __restrict__ b1,
                       const float* __restrict__ W2, const float* __restrict__ b2,
                       const float* __restrict__ Wl, const float* __restrict__ bl,
                       int n) {
    int t = blockIdx.x * blockDim.x + threadIdx.x;
    if (t < n) g_cnt[t] = 0;
    if (t < FIN * C2) {
        int r = t >> 3, c = t & 7;
        float acc = 0.0f;
#pragma unroll
        for (int j = 0; j < C1; j++) acc += W1[r * C1 + j] * W2[j * C2 + c];
        g_M[t] = acc;
    }
    if (t == 0) {
        float alpha = 0.0f, beta = bl[0];
#pragma unroll
        for (int k = 0; k < C2; k++) {
            float ck = 0.0f;
#pragma unroll
            for (int j = 0; j < C1; j++) ck += b1[j] * W2[j * C2 + k];
            alpha += ck * Wl[k];
            beta  += b2[k] * Wl[k];
        }
        g_alpha = alpha;
        g_beta  = beta;
    }
}

// K1: integer degree count, 4 edges/thread
__global__ void k_deg(const int* __restrict__ dst, int E) {
    int t = blockIdx.x * blockDim.x + threadIdx.x;
    int e0 = t * 4;
    if (e0 + 3 < E) {
        int4 d4 = reinterpret_cast<const int4*>(dst)[t];
        atomicAdd(&g_cnt[d4.x], 1);
        atomicAdd(&g_cnt[d4.y], 1);
        atomicAdd(&g_cnt[d4.z], 1);
        atomicAdd(&g_cnt[d4.w], 1);
    } else {
        for (int e = e0; e < E; e++) atomicAdd(&g_cnt[dst[e]], 1);
    }
}

// K2a: per-block exclusive scan of g_cnt (SCAN_B elems/block)
__global__ __launch_bounds__(SCAN_B) void k_scan_a(int n) {
    __shared__ int sh[2 * SCAN_B];
    int t = threadIdx.x;
    int i = blockIdx.x * SCAN_B + t;
    int v = (i < n) ? g_cnt[i] : 0;
    int cur = 0;
    sh[t] = v;
    __syncthreads();
#pragma unroll
    for (int off = 1; off < SCAN_B; off <<= 1) {
        int x = sh[cur + t];
        if (t >= off) x += sh[cur + t - off];
        cur ^= SCAN_B;
        sh[cur + t] = x;
        __syncthreads();
    }
    int inc = sh[cur + t];
    if (i < n) g_off[i] = inc - v;           // block-local exclusive
    if (t == SCAN_B - 1) g_bsum[blockIdx.x] = inc;
}

// K2b: exclusive scan of block sums (single block)
__global__ __launch_bounds__(128) void k_scan_b(int nb) {
    __shared__ int sh[2 * 128];
    int t = threadIdx.x;
    int v = (t < nb) ? g_bsum[t] : 0;
    int cur = 0;
    sh[t] = v;
    __syncthreads();
#pragma unroll
    for (int off = 1; off < 128; off <<= 1) {
        int x = sh[cur + t];
        if (t >= off) x += sh[cur + t - off];
        cur ^= 128;
        sh[cur + t] = x;
        __syncthreads();
    }
    if (t < nb) g_bsum[t] = sh[cur + t] - v;  // exclusive
}

// K2c: finalize offsets, init cursors, compute dinv
__global__ void k_scan_c(int n) {
    int i = blockIdx.x * blockDim.x + threadIdx.x;
    if (i >= n) return;
    int off = g_off[i] + g_bsum[i / SCAN_B];
    g_off[i] = off;
    g_cur[i] = off;
    g_dinv[i] = rsqrtf((float)g_cnt[i] + 1.0f);
}

// K3: CSR build — bin[{pos}] = {src, w}
__global__ void k_build(const int* __restrict__ src,
                        const int* __restrict__ dst, int E) {
    int e = blockIdx.x * blockDim.x + threadIdx.x;
    if (e >= E) return;
    int s = src[e];
    int d = dst[e];
    float w = g_dinv[s] * g_dinv[d];
    int p = atomicAdd(&g_cur[d], 1);
    g_bin[p] = make_int2(s, __float_as_int(w));
}

// K4: u = x @ M  [N,8] (cp.async staging, repacked M)
#define XPAD 33
#define MQ   33
__global__ __launch_bounds__(256) void k_gemm_u(const float* __restrict__ x, int n) {
    __shared__ float4 xs4[NPB * XPAD];
    __shared__ float2 Mp[4 * MQ * 4];

    for (int t = threadIdx.x; t < FIN * 4; t += 256) {
        int k = t >> 2, q = t & 3;
        Mp[(q * MQ + (k >> 2)) * 4 + (k & 3)] =
            make_float2(g_M[k * C2 + 2 * q], g_M[k * C2 + 2 * q + 1]);
    }

    int base = blockIdx.x * NPB;
    int rows = n - base; if (rows > NPB) rows = NPB;

    const float4* xg = reinterpret_cast<const float4*>(x + (size_t)base * FIN);
    unsigned int xs_base = (unsigned int)__cvta_generic_to_shared(xs4);
    int total4 = rows * (FIN / 4);
#pragma unroll
    for (int t = threadIdx.x; t < total4; t += 256)
        cp_async16(xs_base + (unsigned int)(((t >> 5) * XPAD + (t & 31)) * 16), xg + t);
    asm volatile("cp.async.commit_group;\n" ::: "memory");
    asm volatile("cp.async.wait_group 0;\n" ::: "memory");
    __syncthreads();

    int j = threadIdx.x >> 2;
    int q = threadIdx.x & 3;
    float2 acc = make_float2(0.f, 0.f);

    const float4* xr = &xs4[j * XPAD];
    const float4* mq = reinterpret_cast<const float4*>(&Mp[q * MQ * 4]);
#pragma unroll
    for (int k4 = 0; k4 < FIN / 4; k4++) {
        float4 v  = xr[k4];
        float4 mA = mq[k4 * 2 + 0];
        float4 mB = mq[k4 * 2 + 1];
        acc.x += v.x * mA.x + v.y * mA.z + v.z * mB.x + v.w * mB.z;
        acc.y += v.x * mA.y + v.y * mA.w + v.z * mB.y + v.w * mB.w;
    }

    if (j < rows)
        reinterpret_cast<float2*>(g_u)[(base + j) * 4 + q] = acc;
}

// K5: agg layer 1 — warp per node: v[i] = dinv^2 u[i] + sum w*u[s]. No atomics.
__global__ __launch_bounds__(256) void k_agg1(int n) {
    int warp = (blockIdx.x * blockDim.x + threadIdx.x) >> 5;
    int lane = threadIdx.x & 31;
    if (warp >= n) return;
    int off = g_off[warp];
    int cnt = g_cnt[warp];
    float a0=0,a1=0,a2=0,a3=0,a4=0,a5=0,a6=0,a7=0;
    for (int k = lane; k < cnt; k += 32) {
        int2 b = g_bin[off + k];
        float w = __int_as_float(b.y);
        const float4* uu = reinterpret_cast<const float4*>(&g_u[b.x * C2]);
        float4 A = uu[0], B = uu[1];
        a0 += w*A.x; a1 += w*A.y; a2 += w*A.z; a3 += w*A.w;
        a4 += w*B.x; a5 += w*B.y; a6 += w*B.z; a7 += w*B.w;
    }
#pragma unroll
    for (int o = 16; o; o >>= 1) {
        a0 += __shfl_xor_sync(0xffffffffu, a0, o);
        a1 += __shfl_xor_sync(0xffffffffu, a1, o);
        a2 += __shfl_xor_sync(0xffffffffu, a2, o);
        a3 += __shfl_xor_sync(0xffffffffu, a3, o);
        a4 += __shfl_xor_sync(0xffffffffu, a4, o);
        a5 += __shfl_xor_sync(0xffffffffu, a5, o);
        a6 += __shfl_xor_sync(0xffffffffu, a6, o);
        a7 += __shfl_xor_sync(0xffffffffu, a7, o);
    }
    if (lane == 0) {
        float dv = g_dinv[warp];
        float ww = dv * dv;
        const float4* uu = reinterpret_cast<const float4*>(&g_u[warp * C2]);
        float4 A = uu[0], B = uu[1];
        float4* vv = reinterpret_cast<float4*>(&g_v[warp * C2]);
        vv[0] = make_float4(a0 + ww*A.x, a1 + ww*A.y, a2 + ww*A.z, a3 + ww*A.w);
        vv[1] = make_float4(a4 + ww*B.x, a5 + ww*B.y, a6 + ww*B.z, a7 + ww*B.w);
    }
}

// K6: agg layer 2 + head fused — warp per node:
// g = dinv^2 v[i] + sum w*v[s];  sumw = sum w;  z = sigmoid(g·Wl + sfull*alpha + beta)
__global__ __launch_bounds__(256) void k_agg2(const float* __restrict__ Wl, int n) {
    int warp = (blockIdx.x * blockDim.x + threadIdx.x) >> 5;
    int lane = threadIdx.x & 31;
    if (warp >= n) return;
    int off = g_off[warp];
    int cnt = g_cnt[warp];
    float a0=0,a1=0,a2=0,a3=0,a4=0,a5=0,a6=0,a7=0,sw=0;
    for (int k = lane; k < cnt; k += 32) {
        int2 b = g_bin[off + k];
        float w = __int_as_float(b.y);
        sw += w;
        const float4* vv = reinterpret_cast<const float4*>(&g_v[b.x * C2]);
        float4 A = vv[0], B = vv[1];
        a0 += w*A.x; a1 += w*A.y; a2 += w*A.z; a3 += w*A.w;
        a4 += w*B.x; a5 += w*B.y; a6 += w*B.z; a7 += w*B.w;
    }
#pragma unroll
    for (int o = 16; o; o >>= 1) {
        a0 += __shfl_xor_sync(0xffffffffu, a0, o);
        a1 += __shfl_xor_sync(0xffffffffu, a1, o);
        a2 += __shfl_xor_sync(0xffffffffu, a2, o);
        a3 += __shfl_xor_sync(0xffffffffu, a3, o);
        a4 += __shfl_xor_sync(0xffffffffu, a4, o);
        a5 += __shfl_xor_sync(0xffffffffu, a5, o);
        a6 += __shfl_xor_sync(0xffffffffu, a6, o);
        a7 += __shfl_xor_sync(0xffffffffu, a7, o);
        sw += __shfl_xor_sync(0xffffffffu, sw, o);
    }
    if (lane == 0) {
        float dv = g_dinv[warp];
        float ww = dv * dv;
        const float4* vv = reinterpret_cast<const float4*>(&g_v[warp * C2]);
        float4 A = vv[0], B = vv[1];
        float g0 = a0 + ww*A.x, g1 = a1 + ww*A.y, g2 = a2 + ww*A.z, g3 = a3 + ww*A.w;
        float g4 = a4 + ww*B.x, g5 = a5 + ww*B.y, g6 = a6 + ww*B.z, g7 = a7 + ww*B.w;
        float sfull = sw + ww;
        float acc = g_beta + sfull * g_alpha
                  + g0 * Wl[0] + g1 * Wl[1] + g2 * Wl[2] + g3 * Wl[3]
                  + g4 * Wl[4] + g5 * Wl[5] + g6 * Wl[6] + g7 * Wl[7];
        g_z[warp] = 1.0f / (1.0f + expf(-acc));
    }
}

// K7: pred[p] = z[pe[p,0]] * z[pe[p,1]]
__global__ void k_pred(const int* __restrict__ pe,
                       float* __restrict__ out, int P) {
    int p = blockIdx.x * blockDim.x + threadIdx.x;
    if (p >= P) return;
    int2 ab = reinterpret_cast<const int2*>(pe)[p];
    out[p] = g_z[ab.x] * g_z[ab.y];
}

extern "C" void kernel_launch(void* const* d_in, const int* in_sizes, int n_in,
                              void* d_out, int out_size) {
    const float* x   = (const float*)d_in[0];
    const int*   ei  = (const int*)d_in[1];
    const int*   pe  = (const int*)d_in[2];
    const float* W1  = (const float*)d_in[3];
    const float* b1  = (const float*)d_in[4];
    const float* W2  = (const float*)d_in[5];
    const float* b2  = (const float*)d_in[6];
    const float* Wl  = (const float*)d_in[7];
    const float* bl  = (const float*)d_in[8];
    float* out = (float*)d_out;

    int n = in_sizes[0] / FIN;
    int E = in_sizes[1] / 2;
    int P = in_sizes[2] / 2;
    if (E > EMAX) E = EMAX;

    const int* src = ei;
    const int* dst = ei + E;

    const int T = 256;
    int nb = (n + SCAN_B - 1) / SCAN_B;

    k_init  <<<(n + T - 1) / T, T>>>(W1, b1, W2, b2, Wl, bl, n);
    k_deg   <<<(E / 4 + T - 1) / T, T>>>(dst, E);
    k_scan_a<<<nb, SCAN_B>>>(n);
    k_scan_b<<<1, 128>>>(nb);
    k_scan_c<<<(n + T - 1) / T, T>>>(n);
    k_build <<<(E + T - 1) / T, T>>>(src, dst, E);
    k_gemm_u<<<(n + NPB - 1) / NPB, 256>>>(x, n);
    k_agg1  <<<(n * 32 + T - 1) / T, T>>>(n);
    k_agg2  <<<(n * 32 + T - 1) / T, T>>>(Wl, n);
    k_pred  <<<(P + T - 1) / T, T>>>(pe, out, P);
}

// round 10
// speedup vs baseline: 1.7146x; 1.7146x over previous
#include <cuda_runtime.h>
#include <cstdint>
#include <math.h>

#define NMAX  100000
#define EMAX  3200000
#define FIN   128
#define C1    16
#define C2    8

// Scratch (device globals; allocation-free per harness rules)
__device__ __align__(16) int    g_deg [NMAX];
__device__ __align__(16) float  g_dinv[NMAX];
__device__ __align__(16) float  g_y   [NMAX];   // y = x @ m
__device__ __align__(16) float2 g_acc1[NMAX];   // {A_hat y accum, A_hat 1 accum}
__device__ __align__(16) float  g_v   [NMAX];   // v = A_hat y
__device__ __align__(16) float  g_gg  [NMAX];   // A_hat v accum
__device__ __align__(16) float  g_sf  [NMAX];   // sfull = (A_hat 1)
__device__ __align__(16) float  g_z   [NMAX];
__device__ __align__(16) float  g_w   [EMAX];   // per-edge norm weight
__device__ __align__(16) float  g_m   [FIN];    // W1 @ W2 @ Wl
__device__ float g_alpha, g_beta;

// Scalar + v2 fp32 reductions (no return)
__device__ __forceinline__ void red_add_v2(float2* addr, float a, float b) {
    asm volatile(
        "{\n\t"
        ".reg .u64 ga;\n\t"
        "cvta.to.global.u64 ga, %0;\n\t"
        "red.global.add.v2.f32 [ga], {%1, %2};\n\t"
        "}"
        :: "l"(addr), "f"(a), "f"(b) : "memory");
}
__device__ __forceinline__ void red_add_f(float* addr, float a) {
    asm volatile(
        "{\n\t"
        ".reg .u64 ga;\n\t"
        "cvta.to.global.u64 ga, %0;\n\t"
        "red.global.add.f32 [ga], %1;\n\t"
        "}"
        :: "l"(addr), "f"(a) : "memory");
}

// ---------------------------------------------------------------------------
// K0: zero degree counters + fold all weights to m[128], alpha, beta
__global__ void k_init(const float* __restrict__ W1, const float* __restrict__ b1,
                       const float* __restrict__ W2, const float* __restrict__ b2,
                       const float* __restrict__ Wl, const float* __restrict__ bl,
                       int n) {
    int t = blockIdx.x * blockDim.x + threadIdx.x;
    if (t < n) g_deg[t] = 0;
    if (t < FIN) {
        float acc = 0.0f;
#pragma unroll
        for (int j = 0; j < C1; j++) {
            float w1 = W1[t * C1 + j];
            float inner = 0.0f;
#pragma unroll
            for (int k = 0; k < C2; k++) inner += W2[j * C2 + k] * Wl[k];
            acc += w1 * inner;
        }
        g_m[t] = acc;
    }
    if (t == 0) {
        float alpha = 0.0f, beta = bl[0];
#pragma unroll
        for (int k = 0; k < C2; k++) {
            float ck = 0.0f;
#pragma unroll
            for (int j = 0; j < C1; j++) ck += b1[j] * W2[j * C2 + k];
            alpha += ck * Wl[k];
            beta  += b2[k] * Wl[k];
        }
        g_alpha = alpha;
        g_beta  = beta;
    }
}

// K1: integer degree count, 4 edges/thread
__global__ void k_deg(const int* __restrict__ dst, int E) {
    int t = blockIdx.x * blockDim.x + threadIdx.x;
    int e0 = t * 4;
    if (e0 + 3 < E) {
        int4 d4 = reinterpret_cast<const int4*>(dst)[t];
        atomicAdd(&g_deg[d4.x], 1);
        atomicAdd(&g_deg[d4.y], 1);
        atomicAdd(&g_deg[d4.z], 1);
        atomicAdd(&g_deg[d4.w], 1);
    } else {
        for (int e = e0; e < E; e++) atomicAdd(&g_deg[dst[e]], 1);
    }
}

// K2: warp-per-node scalar GEMM: y[i] = x[i]·m; emits dinv and agg1 seeds.
// Each warp reads one 512B row fully coalesced (32 lanes x float4).
__global__ __launch_bounds__(256) void k_gemm_y(const float* __restrict__ x, int n) {
    int warp = (blockIdx.x * blockDim.x + threadIdx.x) >> 5;
    int lane = threadIdx.x & 31;
    if (warp >= n) return;
    float4 xv = reinterpret_cast<const float4*>(x)[warp * 32 + lane];
    float4 mv = reinterpret_cast<const float4*>(g_m)[lane];
    float p = xv.x * mv.x + xv.y * mv.y + xv.z * mv.z + xv.w * mv.w;
#pragma unroll
    for (int o = 16; o; o >>= 1) p += __shfl_xor_sync(0xffffffffu, p, o);
    if (lane == 0) {
        float dv = rsqrtf((float)g_deg[warp] + 1.0f);
        g_dinv[warp] = dv;
        g_y[warp]    = p;
        // seeds: self-loop term dv^2*y, and dv (so sfull = dv*(acc+?) -> see k_mid)
        g_acc1[warp] = make_float2(dv * dv * p, dv);
    }
}

// K3: agg layer 1 — per edge: acc1[d] += {w*y[s], dinv[s]}; stores w for agg2
__global__ void k_agg1(const int* __restrict__ src,
                       const int* __restrict__ dst, int E) {
    int e = blockIdx.x * blockDim.x + threadIdx.x;
    if (e >= E) return;
    int s = src[e];
    int d = dst[e];
    float ds = g_dinv[s];
    float w  = ds * g_dinv[d];
    g_w[e] = w;
    red_add_v2(&g_acc1[d], w * g_y[s], ds);
}

// K4: finalize layer 1: v = acc1.x ; seed layer-2 acc gg = dinv^2*v ; sfull = dinv*acc1.y
__global__ void k_mid(int n) {
    int i = blockIdx.x * blockDim.x + threadIdx.x;
    if (i >= n) return;
    float2 a = g_acc1[i];
    float dv = g_dinv[i];
    g_v[i]  = a.x;
    g_gg[i] = dv * dv * a.x;
    g_sf[i] = dv * a.y;          // = dinv*sum(dinv_s) + dinv^2
}

// K5: agg layer 2 — per edge: gg[d] += w * v[s]
__global__ void k_agg2(const int* __restrict__ src,
                       const int* __restrict__ dst, int E) {
    int e = blockIdx.x * blockDim.x + threadIdx.x;
    if (e >= E) return;
    int s = src[e];
    int d = dst[e];
    red_add_f(&g_gg[d], g_w[e] * g_v[s]);
}

// K6: z = sigmoid(gg + alpha*sfull + beta)
__global__ void k_head(int n) {
    int i = blockIdx.x * blockDim.x + threadIdx.x;
    if (i >= n) return;
    float acc = g_gg[i] + g_alpha * g_sf[i] + g_beta;
    g_z[i] = 1.0f / (1.0f + expf(-acc));
}

// K7: pred[p] = z[pe[p,0]] * z[pe[p,1]]
__global__ void k_pred(const int* __restrict__ pe,
                       float* __restrict__ out, int P) {
    int p = blockIdx.x * blockDim.x + threadIdx.x;
    if (p >= P) return;
    int2 ab = reinterpret_cast<const int2*>(pe)[p];
    out[p] = g_z[ab.x] * g_z[ab.y];
}

extern "C" void kernel_launch(void* const* d_in, const int* in_sizes, int n_in,
                              void* d_out, int out_size) {
    const float* x   = (const float*)d_in[0];
    const int*   ei  = (const int*)d_in[1];
    const int*   pe  = (const int*)d_in[2];
    const float* W1  = (const float*)d_in[3];
    const float* b1  = (const float*)d_in[4];
    const float* W2  = (const float*)d_in[5];
    const float* b2  = (const float*)d_in[6];
    const float* Wl  = (const float*)d_in[7];
    const float* bl  = (const float*)d_in[8];
    float* out = (float*)d_out;

    int n = in_sizes[0] / FIN;
    int E = in_sizes[1] / 2;
    int P = in_sizes[2] / 2;
    if (E > EMAX) E = EMAX;

    const int* src = ei;
    const int* dst = ei + E;

    const int T = 256;

    k_init  <<<(n + T - 1) / T, T>>>(W1, b1, W2, b2, Wl, bl, n);
    k_deg   <<<(E / 4 + T - 1) / T, T>>>(dst, E);
    k_gemm_y<<<(n * 32 + T - 1) / T, T>>>(x, n);
    k_agg1  <<<(E + T - 1) / T, T>>>(src, dst, E);
    k_mid   <<<(n + T - 1) / T, T>>>(n);
    k_agg2  <<<(E + T - 1) / T, T>>>(src, dst, E);
    k_head  <<<(n + T - 1) / T, T>>>(n);
    k_pred  <<<(P + T - 1) / T, T>>>(pe, out, P);
}

// round 11
// speedup vs baseline: 2.0339x; 1.1862x over previous
#include <cuda_runtime.h>
#include <cstdint>
#include <math.h>

#define NMAX  100000
#define EMAX  3200000
#define FIN   128
#define C1    16
#define C2    8

// Scratch (device globals; allocation-free per harness rules)
__device__ __align__(16) int    g_deg [NMAX];
__device__ __align__(16) float2 g_nd1 [NMAX];   // {ys = dinv*y, dinv}
__device__ __align__(16) float2 g_acc [NMAX];   // {Σ ys, Σ dinv_s} (seeded w/ self)
__device__ __align__(16) float  g_dinv[NMAX];
__device__ __align__(16) float  g_p   [NMAX];   // p = dinv*v (agg2 gather src)
__device__ __align__(16) float  g_gg  [NMAX];   // layer-2 accum (seeded w/ p)
__device__ __align__(16) float  g_sf  [NMAX];   // sfull
__device__ __align__(16) float  g_z   [NMAX];
__device__ __align__(16) float  g_m   [FIN];    // W1 @ W2 @ Wl
__device__ float g_alpha, g_beta;

// fp32 reductions, no return
__device__ __forceinline__ void red_add_v2(float2* addr, float a, float b) {
    asm volatile(
        "{\n\t"
        ".reg .u64 ga;\n\t"
        "cvta.to.global.u64 ga, %0;\n\t"
        "red.global.add.v2.f32 [ga], {%1, %2};\n\t"
        "}"
        :: "l"(addr), "f"(a), "f"(b) : "memory");
}
__device__ __forceinline__ void red_add_f(float* addr, float a) {
    asm volatile(
        "{\n\t"
        ".reg .u64 ga;\n\t"
        "cvta.to.global.u64 ga, %0;\n\t"
        "red.global.add.f32 [ga], %1;\n\t"
        "}"
        :: "l"(addr), "f"(a) : "memory");
}

// ---------------------------------------------------------------------------
// K0: zero degree counters + fold all weights to m[128], alpha, beta
__global__ void k_init(const float* __restrict__ W1, const float* __restrict__ b1,
                       const float* __restrict__ W2, const float* __restrict__ b2,
                       const float* __restrict__ Wl, const float* __restrict__ bl,
                       int n) {
    int t = blockIdx.x * blockDim.x + threadIdx.x;
    if (t < n) g_deg[t] = 0;
    if (t < FIN) {
        float acc = 0.0f;
#pragma unroll
        for (int j = 0; j < C1; j++) {
            float w1 = W1[t * C1 + j];
            float inner = 0.0f;
#pragma unroll
            for (int k = 0; k < C2; k++) inner += W2[j * C2 + k] * Wl[k];
            acc += w1 * inner;
        }
        g_m[t] = acc;
    }
    if (t == 0) {
        float alpha = 0.0f, beta = bl[0];
#pragma unroll
        for (int k = 0; k < C2; k++) {
            float ck = 0.0f;
#pragma unroll
            for (int j = 0; j < C1; j++) ck += b1[j] * W2[j * C2 + k];
            alpha += ck * Wl[k];
            beta  += b2[k] * Wl[k];
        }
        g_alpha = alpha;
        g_beta  = beta;
    }
}

// K1: integer degree count, 4 edges/thread
__global__ void k_deg(const int* __restrict__ dst, int E) {
    int t = blockIdx.x * blockDim.x + threadIdx.x;
    int e0 = t * 4;
    if (e0 + 3 < E) {
        int4 d4 = reinterpret_cast<const int4*>(dst)[t];
        atomicAdd(&g_deg[d4.x], 1);
        atomicAdd(&g_deg[d4.y], 1);
        atomicAdd(&g_deg[d4.z], 1);
        atomicAdd(&g_deg[d4.w], 1);
    } else {
        for (int e = e0; e < E; e++) atomicAdd(&g_deg[dst[e]], 1);
    }
}

// K2: warp-per-node: y = x·m; emit nd1 = {dinv*y, dinv}, seed acc with it.
__global__ __launch_bounds__(256) void k_gemm_y(const float* __restrict__ x, int n) {
    int warp = (blockIdx.x * blockDim.x + threadIdx.x) >> 5;
    int lane = threadIdx.x & 31;
    if (warp >= n) return;
    float4 xv = reinterpret_cast<const float4*>(x)[warp * 32 + lane];
    float4 mv = reinterpret_cast<const float4*>(g_m)[lane];
    float p = xv.x * mv.x + xv.y * mv.y + xv.z * mv.z + xv.w * mv.w;
#pragma unroll
    for (int o = 16; o; o >>= 1) p += __shfl_xor_sync(0xffffffffu, p, o);
    if (lane == 0) {
        float dv = rsqrtf((float)g_deg[warp] + 1.0f);
        float2 nd = make_float2(dv * p, dv);
        g_dinv[warp] = dv;
        g_nd1[warp]  = nd;
        g_acc[warp]  = nd;    // self-loop seed: dinv*y, dinv
    }
}

// K3: agg layer 1 — per edge: acc[d] += {ys[s], dinv[s]} (one 8B gather, one red.v2)
__global__ void k_agg1(const int* __restrict__ src,
                       const int* __restrict__ dst, int E) {
    int e = blockIdx.x * blockDim.x + threadIdx.x;
    if (e >= E) return;
    int s = src[e];
    int d = dst[e];
    float2 nd = g_nd1[s];
    red_add_v2(&g_acc[d], nd.x, nd.y);
}

// K4: finalize layer 1 + seed layer 2:
// v = dinv*acc.x ; p = dinv*v ; gg seed = p ; sfull = dinv*acc.y
__global__ void k_mid(int n) {
    int i = blockIdx.x * blockDim.x + threadIdx.x;
    if (i >= n) return;
    float2 a = g_acc[i];
    float dv = g_dinv[i];
    float p  = dv * dv * a.x;    // dinv * v, v = dinv*acc.x
    g_p[i]  = p;
    g_gg[i] = p;                 // self-loop seed for layer 2
    g_sf[i] = dv * a.y;
}

// K5: agg layer 2 — per edge: gg[d] += p[s] (one 4B gather, one scalar red)
__global__ void k_agg2(const int* __restrict__ src,
                       const int* __restrict__ dst, int E) {
    int e = blockIdx.x * blockDim.x + threadIdx.x;
    if (e >= E) return;
    red_add_f(&g_gg[dst[e]], g_p[src[e]]);
}

// K6: z = sigmoid(dinv*gg + alpha*sfull + beta)
__global__ void k_head(int n) {
    int i = blockIdx.x * blockDim.x + threadIdx.x;
    if (i >= n) return;
    float acc = g_dinv[i] * g_gg[i] + g_alpha * g_sf[i] + g_beta;
    g_z[i] = 1.0f / (1.0f + expf(-acc));
}

// K7: pred[p] = z[pe[p,0]] * z[pe[p,1]]
__global__ void k_pred(const int* __restrict__ pe,
                       float* __restrict__ out, int P) {
    int p = blockIdx.x * blockDim.x + threadIdx.x;
    if (p >= P) return;
    int2 ab = reinterpret_cast<const int2*>(pe)[p];
    out[p] = g_z[ab.x] * g_z[ab.y];
}

extern "C" void kernel_launch(void* const* d_in, const int* in_sizes, int n_in,
                              void* d_out, int out_size) {
    const float* x   = (const float*)d_in[0];
    const int*   ei  = (const int*)d_in[1];
    const int*   pe  = (const int*)d_in[2];
    const float* W1  = (const float*)d_in[3];
    const float* b1  = (const float*)d_in[4];
    const float* W2  = (const float*)d_in[5];
    const float* b2  = (const float*)d_in[6];
    const float* Wl  = (const float*)d_in[7];
    const float* bl  = (const float*)d_in[8];
    float* out = (float*)d_out;

    int n = in_sizes[0] / FIN;
    int E = in_sizes[1] / 2;
    int P = in_sizes[2] / 2;
    if (E > EMAX) E = EMAX;

    const int* src = ei;
    const int* dst = ei + E;

    const int T = 256;

    k_init  <<<(n + T - 1) / T, T>>>(W1, b1, W2, b2, Wl, bl, n);
    k_deg   <<<(E / 4 + T - 1) / T, T>>>(dst, E);
    k_gemm_y<<<(n * 32 + T - 1) / T, T>>>(x, n);
    k_agg1  <<<(E + T - 1) / T, T>>>(src, dst, E);
    k_mid   <<<(n + T - 1) / T, T>>>(n);
    k_agg2  <<<(E + T - 1) / T, T>>>(src, dst, E);
    k_head  <<<(n + T - 1) / T, T>>>(n);
    k_pred  <<<(P + T - 1) / T, T>>>(pe, out, P);
}